// round 14
// baseline (speedup 1.0000x reference)
#include <cuda_runtime.h>
#include <cuda_fp16.h>
#include <cstdint>

// ============================================================================
// LSTM decoder, B=2048, T=32, H=1024, inference path (pred feedback).
// sm_100: fp16 mma.sync GEMM + cp.async 3-stage pipeline.
//
// R14: CTA tile 128x256 (512 thr, 16 warps, warp tile 64x32, 1 CTA/SM) — the
// R3/R4 shape that measured 262 TF/s — at K=1024, plus all R10/R12 trims:
//  - PDL: pre-wait prefetch of ALL 3 B stages + const staging; A after wait.
//    Groups {B0}{B1}{B2}|wait|{A0}{A1}; c=0 issues {A2}, c>=1 fused {A,B}(c+2).
//  - predsum folded into d_out (init = fc_b in prep; prev read from d_out).
//  - Halved STS traffic vs 2x(128x128): 48KB cp.async per chunk per SM.
// W columns permuted: col n -> (unit n>>2, gate n&3), gate order i,f,g,o.
// h double-buffered across steps (cross-CTA race fix).
// ============================================================================

#define BATCH 2048
#define TT    32
#define HH    1024
#define N4    4096
#define KE    1024            // K = H (single fp16 term)
#define TM    128             // M tile
#define TN    256             // N tile
#define KC    64              // K chunk (fp16) = 128 bytes
#define NCH   (KE / KC)       // 16
#define NTHREADS 512
#define STAGES 3
#define STAGE_BYTES 49152     // A 16KB + B 32KB
#define STAGING_BYTES 3584    // bias/w0/w1 float4[64] + fcW float[64]
#define SMEM_BYTES  (1024 + STAGES * STAGE_BYTES + STAGING_BYTES)  // ~149KB -> 1 CTA/SM
#define GPITCH 132            // gates smem pitch (floats), proven R4

// Scratch (device globals; no allocation allowed)
__device__ __align__(256) __half g_Wext[(size_t)N4 * KE];        // 8 MB
__device__ __align__(256) __half g_Aext[2][(size_t)BATCH * KE];  // 2 x 4 MB
__device__ __align__(256) float g_c[(size_t)BATCH * HH];         // 8 MB
__device__ __align__(256) float g_bias[N4];
__device__ __align__(256) float g_w0[N4];
__device__ __align__(256) float g_w1[N4];
__device__ __align__(256) float g_fcW[HH];

// ---------------------------------------------------------------------------
// helpers
// ---------------------------------------------------------------------------
__device__ __forceinline__ uint32_t smem_u32(const void* p) {
    uint32_t a;
    asm("{ .reg .u64 t; cvta.to.shared.u64 t, %1; cvt.u32.u64 %0, t; }" : "=r"(a) : "l"(p));
    return a;
}
__device__ __forceinline__ void cp_async16(uint32_t dst, const void* src) {
    asm volatile("cp.async.cg.shared.global [%0], [%1], 16;" :: "r"(dst), "l"(src) : "memory");
}
__device__ __forceinline__ void cp_commit() {
    asm volatile("cp.async.commit_group;" ::: "memory");
}
__device__ __forceinline__ uint32_t sw128(uint32_t off) {
    return off ^ ((off >> 3) & 0x70u);
}
__device__ __forceinline__ void ldsm_x4(uint32_t& r0, uint32_t& r1, uint32_t& r2, uint32_t& r3,
                                        uint32_t addr) {
    asm volatile("ldmatrix.sync.aligned.m8n8.x4.shared.b16 {%0,%1,%2,%3}, [%4];"
                 : "=r"(r0), "=r"(r1), "=r"(r2), "=r"(r3) : "r"(addr));
}
__device__ __forceinline__ void mma_fp16(float* d, const uint32_t* a, const uint32_t* b) {
    asm volatile(
        "mma.sync.aligned.m16n8k16.row.col.f32.f16.f16.f32 "
        "{%0,%1,%2,%3}, {%4,%5,%6,%7}, {%8,%9}, {%0,%1,%2,%3};"
        : "+f"(d[0]), "+f"(d[1]), "+f"(d[2]), "+f"(d[3])
        : "r"(a[0]), "r"(a[1]), "r"(a[2]), "r"(a[3]), "r"(b[0]), "r"(b[1]));
}
__device__ __forceinline__ float sigf(float x) {
    return __fdividef(1.0f, 1.0f + __expf(-x));
}
__device__ __forceinline__ float tanh_f(float x) {
    float xc = fminf(fmaxf(x, -15.0f), 15.0f);
    float e = __expf(2.0f * xc);
    return 1.0f - __fdividef(2.0f, e + 1.0f);
}

// ---------------------------------------------------------------------------
// Prep kernels
// ---------------------------------------------------------------------------
__global__ void prep_weights(const float* __restrict__ W_hh, const float* __restrict__ W_ih,
                             const float* __restrict__ b_ih, const float* __restrict__ b_hh,
                             const float* __restrict__ fc_W) {
    int idx = blockIdx.x * blockDim.x + threadIdx.x;   // 0 .. 4096*1024-1
    int n = idx >> 10, k = idx & 1023;
    int r = (n & 3) * HH + (n >> 2);                   // col n -> orig W_hh row
    g_Wext[(size_t)n * KE + k] = __float2half(W_hh[(size_t)r * HH + k]);
    if (idx < N4) {
        int rr = (idx & 3) * HH + (idx >> 2);
        g_bias[idx] = b_ih[rr] + b_hh[rr];
        g_w0[idx] = W_ih[rr * 2 + 0];
        g_w1[idx] = W_ih[rr * 2 + 1];
    }
    if (idx < HH) g_fcW[idx] = fc_W[idx];
}

__global__ void prep_state(const float* __restrict__ hidden, const float* __restrict__ cell,
                           float* __restrict__ out, const float* __restrict__ fc_b) {
    int idx = blockIdx.x * blockDim.x + threadIdx.x;   // 0 .. 2048*1024-1
    g_c[idx] = cell[idx];
    g_Aext[0][idx] = __float2half(hidden[idx]);
    if (idx < BATCH * TT) out[idx] = fc_b[0];          // predsum accumulates on top
}

// ---------------------------------------------------------------------------
// Step kernel: GEMM (tile 128x256, K=1024) + fused LSTM cell epilogue
// 512 threads = 16 warps; warp tile 64x32: warp_m = wid&1, warp_n = wid>>1.
// ---------------------------------------------------------------------------
__global__ void __launch_bounds__(NTHREADS, 1)
step_kernel(int t, const float* __restrict__ future_fd, float* __restrict__ out) {
    const __half* __restrict__ Asrc = g_Aext[t & 1];
    __half* __restrict__ Adst = g_Aext[(t + 1) & 1];

    extern __shared__ char smem_raw[];
    uint32_t sb = smem_u32(smem_raw);
    uint32_t ab = (sb + 1023u) & ~1023u;
    char* smem = smem_raw + (ab - sb);
    const uint32_t tiles = ab;

    const int tid = threadIdx.x;
    const int wid = tid >> 5;
    const int lid = tid & 31;
    const int wm = wid & 1;          // 0..1  (64-row block)
    const int wn = wid >> 1;         // 0..7  (32-col block)
    const int m0 = blockIdx.x * TM;
    const int n0 = blockIdx.y * TN;
    const int u0 = n0 >> 2;          // first unit of this CTA (64 units)

    // ---- const staging (step-invariant: safe pre-wait) ---------------------
    float4* smB  = (float4*)(smem + STAGES * STAGE_BYTES);   // [64]
    float4* smW0 = smB + 64;                                  // [64]
    float4* smW1 = smB + 128;                                 // [64]
    float*  smFc = (float*)(smB + 192);                       // [64]
    if (tid < 64)        smB[tid]        = ((const float4*)g_bias)[u0 + tid];
    else if (tid < 128)  smW0[tid - 64]  = ((const float4*)g_w0)[u0 + tid - 64];
    else if (tid < 192)  smW1[tid - 128] = ((const float4*)g_w1)[u0 + tid - 128];
    else if (tid < 256)  smFc[tid - 192] = g_fcW[u0 + tid - 192];

    // ---- split chunk loaders ----------------------------------------------
    auto load_A = [&](int c, int s) {          // 128 rows x 128B
        const int k0 = c * KC;
        const uint32_t base = tiles + s * STAGE_BYTES;
        #pragma unroll
        for (int j = 0; j < 2; j++) {
            int li = tid + j * NTHREADS;       // 0..1023
            int ri = li >> 3, q = li & 7;
            uint32_t dst = base + sw128((uint32_t)(ri * 128 + q * 16));
            cp_async16(dst, Asrc + ((size_t)(m0 + ri) * KE + k0 + q * 8));
        }
    };
    auto load_B = [&](int c, int s) {          // 256 rows x 128B
        const int k0 = c * KC;
        const uint32_t base = tiles + s * STAGE_BYTES + 16384;
        #pragma unroll
        for (int j = 0; j < 4; j++) {
            int li = tid + j * NTHREADS;       // 0..2047
            int ri = li >> 3, q = li & 7;
            uint32_t dst = base + sw128((uint32_t)(ri * 128 + q * 16));
            cp_async16(dst, g_Wext + ((size_t)(n0 + ri) * KE + k0 + q * 8));
        }
    };

    // ---- PDL prologue: ALL weight stages prefetch pre-wait -----------------
    load_B(0, 0); cp_commit();                 // group: B0
    load_B(1, 1); cp_commit();                 // group: B1
    load_B(2, 2); cp_commit();                 // group: B2
    asm volatile("griddepcontrol.wait;" ::: "memory");
    load_A(0, 0); cp_commit();                 // group: A0
    load_A(1, 1); cp_commit();                 // group: A1

    // ---- lane constants for ldmatrix addressing ----------------------------
    const int a_lr = lid & 15;
    const int a_ch = (lid >> 4) << 4;
    const int b_nr = (lid & 7) + ((lid >> 4) << 3);
    const int b_ch = ((lid >> 3) & 1) << 4;

    float acc[4][4][4];
    #pragma unroll
    for (int i = 0; i < 4; i++)
        #pragma unroll
        for (int j = 0; j < 4; j++)
            #pragma unroll
            for (int r = 0; r < 4; r++) acc[i][j][r] = 0.0f;

    #pragma unroll 1
    for (int c = 0; c < NCH; c++) {
        // c=0: pending {B0,B1,B2,A0,A1}; wait_group 1 retires B0-B2,A0.
        // c=1: retires A1 (A2 pending). c>=2 steady: retires chunk c's group.
        if (c < NCH - 2) asm volatile("cp.async.wait_group 1;" ::: "memory");
        else             asm volatile("cp.async.wait_group 0;" ::: "memory");
        __syncthreads();

        if (c == 0)              { load_A(2, 2); cp_commit(); }              // B2 already resident
        else if (c + 2 < NCH)    { load_A(c + 2, (c + 2) % STAGES);
                                   load_B(c + 2, (c + 2) % STAGES); cp_commit(); }

        const uint32_t As = tiles + (c % STAGES) * STAGE_BYTES;
        const uint32_t Bs = As + 16384;

        #pragma unroll
        for (int ks = 0; ks < 4; ks++) {
            uint32_t a[4][4], b[4][2];
            #pragma unroll
            for (int mi = 0; mi < 4; mi++) {
                uint32_t off = (uint32_t)((wm * 64 + mi * 16 + a_lr) * 128 + ks * 32 + a_ch);
                ldsm_x4(a[mi][0], a[mi][1], a[mi][2], a[mi][3], As + sw128(off));
            }
            #pragma unroll
            for (int nb = 0; nb < 2; nb++) {
                uint32_t off = (uint32_t)((wn * 32 + nb * 16 + b_nr) * 128 + ks * 32 + b_ch);
                ldsm_x4(b[nb * 2][0], b[nb * 2][1], b[nb * 2 + 1][0], b[nb * 2 + 1][1],
                        Bs + sw128(off));
            }
            #pragma unroll
            for (int mi = 0; mi < 4; mi++)
                #pragma unroll
                for (int j = 0; j < 4; j++)
                    mma_fp16(acc[mi][j], a[mi], b[j]);
        }
    }
    __syncthreads();   // smem stages now reusable as epilogue scratch

    // Next step's CTAs spin up and prefetch weights while we run the epilogue.
    asm volatile("griddepcontrol.launch_dependents;");

    // ---- epilogue: gates -> smem (two 128-col halves), fused cell update ---
    float* gates = (float*)smem;                  // 128 rows x GPITCH floats
    const int g = lid >> 2, tg = lid & 3;

    #pragma unroll 1
    for (int half = 0; half < 2; half++) {
        if ((wn >> 2) == half) {
            const int clb = (wn & 3) * 32;
            #pragma unroll
            for (int mi = 0; mi < 4; mi++) {
                const int r = wm * 64 + mi * 16 + g;
                #pragma unroll
                for (int j = 0; j < 4; j++) {
                    const int cl = clb + j * 8 + 2 * tg;
                    *(float2*)&gates[r * GPITCH + cl]       = make_float2(acc[mi][j][0], acc[mi][j][1]);
                    *(float2*)&gates[(r + 8) * GPITCH + cl] = make_float2(acc[mi][j][2], acc[mi][j][3]);
                }
            }
        }
        __syncthreads();

        #pragma unroll 4
        for (int jj = 0; jj < 8; jj++) {
            const int idx = tid + jj * NTHREADS;       // 4096 = 128 rows x 32 units
            const int row = idx >> 5, u = idx & 31;    // u == lid (warp-row aligned)
            const int lu = half * 32 + u;              // local unit 0..63
            const int ug = u0 + lu;                    // global unit 0..1023
            const int b = m0 + row;

            float4 gv = *(float4*)&gates[row * GPITCH + 4 * u];
            float4 bs = smB[lu];
            float4 w0 = smW0[lu];
            float4 w1 = smW1[lu];

            float prev = (t > 0) ? out[b * TT + (t - 1)] : 0.0f;   // includes fc_b
            const float fdv = future_fd[b * TT + t];

            float gi = gv.x + bs.x + prev * w0.x + fdv * w1.x;
            float gf = gv.y + bs.y + prev * w0.y + fdv * w1.y;
            float gg = gv.z + bs.z + prev * w0.z + fdv * w1.z;
            float go = gv.w + bs.w + prev * w0.w + fdv * w1.w;

            float co = g_c[(size_t)b * HH + ug];
            float cn = sigf(gf) * co + sigf(gi) * tanh_f(gg);
            float h  = sigf(go) * tanh_f(cn);
            g_c[(size_t)b * HH + ug] = cn;
            Adst[(size_t)b * KE + ug] = __float2half(h);

            float fcp = h * smFc[lu];
            #pragma unroll
            for (int o = 16; o; o >>= 1) fcp += __shfl_down_sync(0xFFFFFFFFu, fcp, o);
            if (lid == 0) atomicAdd(&out[b * TT + t], fcp);
        }
        __syncthreads();
    }
}

// ---------------------------------------------------------------------------
// Host launcher
// ---------------------------------------------------------------------------
extern "C" void kernel_launch(void* const* d_in, const int* in_sizes, int n_in,
                              void* d_out, int out_size) {
    const float* future_fd = (const float*)d_in[0];
    const float* hidden    = (const float*)d_in[1];
    const float* cell      = (const float*)d_in[2];
    const float* W_ih      = (const float*)d_in[3];
    const float* W_hh      = (const float*)d_in[4];
    const float* b_ih      = (const float*)d_in[5];
    const float* b_hh      = (const float*)d_in[6];
    const float* fc_W      = (const float*)d_in[7];
    const float* fc_b      = (const float*)d_in[8];
    float* out = (float*)d_out;

    cudaFuncSetAttribute(step_kernel, cudaFuncAttributeMaxDynamicSharedMemorySize, SMEM_BYTES);

    prep_weights<<<(N4 * HH) / 256, 256>>>(W_hh, W_ih, b_ih, b_hh, fc_W);
    prep_state<<<(BATCH * HH) / 256, 256>>>(hidden, cell, out, fc_b);

    cudaLaunchAttribute pdl_attr;
    pdl_attr.id = cudaLaunchAttributeProgrammaticStreamSerialization;
    pdl_attr.val.programmaticStreamSerializationAllowed = 1;

    for (int t = 0; t < TT; t++) {
        cudaLaunchConfig_t cfg = {};
        cfg.gridDim = dim3(BATCH / TM, N4 / TN, 1);
        cfg.blockDim = dim3(NTHREADS, 1, 1);
        cfg.dynamicSmemBytes = SMEM_BYTES;
        cfg.stream = 0;
        if (t > 0) { cfg.attrs = &pdl_attr; cfg.numAttrs = 1; }   // t=0 plain: prep must fully finish
        cudaLaunchKernelEx(&cfg, step_kernel, t, future_fd, out);
    }
}

// round 15
// speedup vs baseline: 1.0969x; 1.0969x over previous
#include <cuda_runtime.h>
#include <cuda_fp16.h>
#include <cstdint>

// ============================================================================
// LSTM decoder, B=2048, T=32, H=1024, inference path (pred feedback).
// sm_100: fp16 mma.sync GEMM + cp.async 3-stage pipeline, 2 CTAs/SM.
// R15 = R13 champion (confirmed-optimal tile 128x128, 8 warps, 2 CTAs/SM,
// PDL with 3-stage B pre-wait prefetch, d_out-folded predsum, smem consts,
// epilogue unroll 4) + smem-staged prev/fdv (removes 32 uniform L2-latency
// loads per warp from the cell-update loop; staged in parallel during the
// gates-store phase).
// W columns permuted: col n -> (unit n>>2, gate n&3), gate order i,f,g,o.
// h double-buffered across steps (cross-CTA race fix).
// ============================================================================

#define BATCH 2048
#define TT    32
#define HH    1024
#define N4    4096
#define KE    1024            // K = H (single fp16 term)
#define TM    128             // M tile
#define TN    128             // N tile
#define KC    64              // K chunk (fp16) = 128 bytes
#define NCH   (KE / KC)       // 16
#define NTHREADS 256
#define STAGES 3
#define STAGE_BYTES 32768     // A 16KB + B 16KB
#define STAGING_BYTES 3072    // consts 1664B + prev/fd 1024B
#define SMEM_BYTES  (1024 + STAGES * STAGE_BYTES + STAGING_BYTES)  // ~100KB -> 2 CTAs/SM
#define GPITCH 132            // gates smem pitch (floats), conflict-free

// Scratch (device globals; no allocation allowed)
__device__ __align__(256) __half g_Wext[(size_t)N4 * KE];        // 8 MB
__device__ __align__(256) __half g_Aext[2][(size_t)BATCH * KE];  // 2 x 4 MB
__device__ __align__(256) float g_c[(size_t)BATCH * HH];         // 8 MB
__device__ __align__(256) float g_bias[N4];
__device__ __align__(256) float g_w0[N4];
__device__ __align__(256) float g_w1[N4];
__device__ __align__(256) float g_fcW[HH];

// ---------------------------------------------------------------------------
// helpers
// ---------------------------------------------------------------------------
__device__ __forceinline__ uint32_t smem_u32(const void* p) {
    uint32_t a;
    asm("{ .reg .u64 t; cvta.to.shared.u64 t, %1; cvt.u32.u64 %0, t; }" : "=r"(a) : "l"(p));
    return a;
}
__device__ __forceinline__ void cp_async16(uint32_t dst, const void* src) {
    asm volatile("cp.async.cg.shared.global [%0], [%1], 16;" :: "r"(dst), "l"(src) : "memory");
}
__device__ __forceinline__ void cp_commit() {
    asm volatile("cp.async.commit_group;" ::: "memory");
}
__device__ __forceinline__ uint32_t sw128(uint32_t off) {
    return off ^ ((off >> 3) & 0x70u);
}
__device__ __forceinline__ void ldsm_x4(uint32_t& r0, uint32_t& r1, uint32_t& r2, uint32_t& r3,
                                        uint32_t addr) {
    asm volatile("ldmatrix.sync.aligned.m8n8.x4.shared.b16 {%0,%1,%2,%3}, [%4];"
                 : "=r"(r0), "=r"(r1), "=r"(r2), "=r"(r3) : "r"(addr));
}
__device__ __forceinline__ void mma_fp16(float* d, const uint32_t* a, const uint32_t* b) {
    asm volatile(
        "mma.sync.aligned.m16n8k16.row.col.f32.f16.f16.f32 "
        "{%0,%1,%2,%3}, {%4,%5,%6,%7}, {%8,%9}, {%0,%1,%2,%3};"
        : "+f"(d[0]), "+f"(d[1]), "+f"(d[2]), "+f"(d[3])
        : "r"(a[0]), "r"(a[1]), "r"(a[2]), "r"(a[3]), "r"(b[0]), "r"(b[1]));
}
__device__ __forceinline__ float sigf(float x) {
    return __fdividef(1.0f, 1.0f + __expf(-x));
}
__device__ __forceinline__ float tanh_f(float x) {
    float xc = fminf(fmaxf(x, -15.0f), 15.0f);
    float e = __expf(2.0f * xc);
    return 1.0f - __fdividef(2.0f, e + 1.0f);
}

// ---------------------------------------------------------------------------
// Prep kernels
// ---------------------------------------------------------------------------
__global__ void prep_weights(const float* __restrict__ W_hh, const float* __restrict__ W_ih,
                             const float* __restrict__ b_ih, const float* __restrict__ b_hh,
                             const float* __restrict__ fc_W) {
    int idx = blockIdx.x * blockDim.x + threadIdx.x;   // 0 .. 4096*1024-1
    int n = idx >> 10, k = idx & 1023;
    int r = (n & 3) * HH + (n >> 2);                   // col n -> orig W_hh row
    g_Wext[(size_t)n * KE + k] = __float2half(W_hh[(size_t)r * HH + k]);
    if (idx < N4) {
        int rr = (idx & 3) * HH + (idx >> 2);
        g_bias[idx] = b_ih[rr] + b_hh[rr];
        g_w0[idx] = W_ih[rr * 2 + 0];
        g_w1[idx] = W_ih[rr * 2 + 1];
    }
    if (idx < HH) g_fcW[idx] = fc_W[idx];
}

__global__ void prep_state(const float* __restrict__ hidden, const float* __restrict__ cell,
                           float* __restrict__ out, const float* __restrict__ fc_b) {
    int idx = blockIdx.x * blockDim.x + threadIdx.x;   // 0 .. 2048*1024-1
    g_c[idx] = cell[idx];
    g_Aext[0][idx] = __float2half(hidden[idx]);
    if (idx < BATCH * TT) out[idx] = fc_b[0];          // predsum accumulates on top
}

// ---------------------------------------------------------------------------
// Step kernel: GEMM (tile 128x128, K=1024) + fused LSTM cell epilogue
// 256 threads = 8 warps; warp tile 64x32: warp_m = wid&1, warp_n = wid>>1.
// ---------------------------------------------------------------------------
__global__ void __launch_bounds__(NTHREADS, 2)
step_kernel(int t, const float* __restrict__ future_fd, float* __restrict__ out) {
    const __half* __restrict__ Asrc = g_Aext[t & 1];
    __half* __restrict__ Adst = g_Aext[(t + 1) & 1];

    extern __shared__ char smem_raw[];
    uint32_t sb = smem_u32(smem_raw);
    uint32_t ab = (sb + 1023u) & ~1023u;
    char* smem = smem_raw + (ab - sb);
    const uint32_t tiles = ab;

    const int tid = threadIdx.x;
    const int wid = tid >> 5;
    const int lid = tid & 31;
    const int wm = wid & 1;          // 0..1  (64-row block)
    const int wn = wid >> 1;         // 0..3  (32-col block)
    const int m0 = blockIdx.x * TM;
    const int n0 = blockIdx.y * TN;
    const int u0 = n0 >> 2;          // first unit of this CTA (32 units)

    // ---- const staging (step-invariant: safe pre-wait) ---------------------
    float4* smB  = (float4*)(smem + STAGES * STAGE_BYTES);   // [32]
    float4* smW0 = smB + 32;
    float4* smW1 = smB + 64;
    float*  smFc = (float*)(smB + 96);                        // [32]
    float*  smPrev = smFc + 32;                               // [128]
    float*  smFd   = smPrev + 128;                            // [128]
    if (tid < 32)        smB[tid]        = ((const float4*)g_bias)[u0 + tid];
    else if (tid < 64)   smW0[tid - 32]  = ((const float4*)g_w0)[u0 + tid - 32];
    else if (tid < 96)   smW1[tid - 64]  = ((const float4*)g_w1)[u0 + tid - 64];
    else if (tid < 128)  smFc[tid - 96]  = g_fcW[u0 + tid - 96];

    // ---- split chunk loaders ----------------------------------------------
    auto load_A = [&](int c, int s) {
        const int k0 = c * KC;
        const uint32_t base = tiles + s * STAGE_BYTES;
        #pragma unroll
        for (int j = 0; j < 4; j++) {
            int li = tid + j * NTHREADS;
            int ri = li >> 3, q = li & 7;
            uint32_t dst = base + sw128((uint32_t)(ri * 128 + q * 16));
            cp_async16(dst, Asrc + ((size_t)(m0 + ri) * KE + k0 + q * 8));
        }
    };
    auto load_B = [&](int c, int s) {
        const int k0 = c * KC;
        const uint32_t base = tiles + s * STAGE_BYTES + 16384;
        #pragma unroll
        for (int j = 0; j < 4; j++) {
            int li = tid + j * NTHREADS;
            int ri = li >> 3, q = li & 7;
            uint32_t dst = base + sw128((uint32_t)(ri * 128 + q * 16));
            cp_async16(dst, g_Wext + ((size_t)(n0 + ri) * KE + k0 + q * 8));
        }
    };

    // ---- PDL prologue: ALL weight stages prefetch pre-wait -----------------
    load_B(0, 0); cp_commit();                 // group: B0
    load_B(1, 1); cp_commit();                 // group: B1
    load_B(2, 2); cp_commit();                 // group: B2
    asm volatile("griddepcontrol.wait;" ::: "memory");
    load_A(0, 0); cp_commit();                 // group: A0
    load_A(1, 1); cp_commit();                 // group: A1

    // ---- lane constants for ldmatrix addressing ----------------------------
    const int a_lr = lid & 15;
    const int a_ch = (lid >> 4) << 4;
    const int b_nr = (lid & 7) + ((lid >> 4) << 3);
    const int b_ch = ((lid >> 3) & 1) << 4;

    float acc[4][4][4];
    #pragma unroll
    for (int i = 0; i < 4; i++)
        #pragma unroll
        for (int j = 0; j < 4; j++)
            #pragma unroll
            for (int r = 0; r < 4; r++) acc[i][j][r] = 0.0f;

    #pragma unroll 1
    for (int c = 0; c < NCH; c++) {
        // c=0: pending {B0,B1,B2,A0,A1}; wait_group 1 retires B0-B2,A0.
        // c=1: retires A1 (A2 may remain). c>=2 steady: retires chunk c's group.
        if (c < NCH - 2) asm volatile("cp.async.wait_group 1;" ::: "memory");
        else             asm volatile("cp.async.wait_group 0;" ::: "memory");
        __syncthreads();

        if (c == 0)              { load_A(2, 2); cp_commit(); }              // B2 already resident
        else if (c + 2 < NCH)    { load_A(c + 2, (c + 2) % STAGES);
                                   load_B(c + 2, (c + 2) % STAGES); cp_commit(); }

        const uint32_t As = tiles + (c % STAGES) * STAGE_BYTES;
        const uint32_t Bs = As + 16384;

        #pragma unroll
        for (int ks = 0; ks < 4; ks++) {
            uint32_t a[4][4], b[4][2];
            #pragma unroll
            for (int mi = 0; mi < 4; mi++) {
                uint32_t off = (uint32_t)((wm * 64 + mi * 16 + a_lr) * 128 + ks * 32 + a_ch);
                ldsm_x4(a[mi][0], a[mi][1], a[mi][2], a[mi][3], As + sw128(off));
            }
            #pragma unroll
            for (int nb = 0; nb < 2; nb++) {
                uint32_t off = (uint32_t)((wn * 32 + nb * 16 + b_nr) * 128 + ks * 32 + b_ch);
                ldsm_x4(b[nb * 2][0], b[nb * 2][1], b[nb * 2 + 1][0], b[nb * 2 + 1][1],
                        Bs + sw128(off));
            }
            #pragma unroll
            for (int mi = 0; mi < 4; mi++)
                #pragma unroll
                for (int j = 0; j < 4; j++)
                    mma_fp16(acc[mi][j], a[mi], b[j]);
        }
    }
    __syncthreads();   // smem stages now reusable as epilogue scratch

    // Next step's CTAs spin up and prefetch weights while we run the epilogue.
    asm volatile("griddepcontrol.launch_dependents;");

    // ---- epilogue: gates -> smem, fused cell update ------------------------
    // Concurrently stage prev/fdv (scattered ~L2-latency loads, full MLP,
    // hidden under the gates stores) so the cell-update loop reads smem only.
    float* gates = (float*)smem;                  // 128 rows x GPITCH floats
    const int g = lid >> 2, tg = lid & 3;

    if (tid < 128) {
        smPrev[tid] = (t > 0) ? out[(m0 + tid) * TT + (t - 1)] : 0.0f;  // includes fc_b
    } else {
        smFd[tid - 128] = future_fd[(m0 + tid - 128) * TT + t];
    }
    {
        const int clb = wn * 32;
        #pragma unroll
        for (int mi = 0; mi < 4; mi++) {
            const int r = wm * 64 + mi * 16 + g;
            #pragma unroll
            for (int j = 0; j < 4; j++) {
                const int cl = clb + j * 8 + 2 * tg;
                *(float2*)&gates[r * GPITCH + cl]       = make_float2(acc[mi][j][0], acc[mi][j][1]);
                *(float2*)&gates[(r + 8) * GPITCH + cl] = make_float2(acc[mi][j][2], acc[mi][j][3]);
            }
        }
    }
    __syncthreads();

    #pragma unroll 4
    for (int jj = 0; jj < 16; jj++) {
        const int idx = tid + jj * NTHREADS;       // 4096 = 128 rows x 32 units
        const int row = idx >> 5, u = idx & 31;
        const int ug = u0 + u;                     // global unit 0..1023
        const int b = m0 + row;

        float4 gv = *(float4*)&gates[row * GPITCH + 4 * u];
        float4 bs = smB[u];
        float4 w0 = smW0[u];
        float4 w1 = smW1[u];

        const float prev = smPrev[row];
        const float fdv  = smFd[row];

        float gi = gv.x + bs.x + prev * w0.x + fdv * w1.x;
        float gf = gv.y + bs.y + prev * w0.y + fdv * w1.y;
        float gg = gv.z + bs.z + prev * w0.z + fdv * w1.z;
        float go = gv.w + bs.w + prev * w0.w + fdv * w1.w;

        float co = g_c[(size_t)b * HH + ug];
        float cn = sigf(gf) * co + sigf(gi) * tanh_f(gg);
        float h  = sigf(go) * tanh_f(cn);
        g_c[(size_t)b * HH + ug] = cn;
        Adst[(size_t)b * KE + ug] = __float2half(h);

        float fcp = h * smFc[u];
        #pragma unroll
        for (int o = 16; o; o >>= 1) fcp += __shfl_down_sync(0xFFFFFFFFu, fcp, o);
        if (lid == 0) atomicAdd(&out[b * TT + t], fcp);
    }
}

// ---------------------------------------------------------------------------
// Host launcher
// ---------------------------------------------------------------------------
extern "C" void kernel_launch(void* const* d_in, const int* in_sizes, int n_in,
                              void* d_out, int out_size) {
    const float* future_fd = (const float*)d_in[0];
    const float* hidden    = (const float*)d_in[1];
    const float* cell      = (const float*)d_in[2];
    const float* W_ih      = (const float*)d_in[3];
    const float* W_hh      = (const float*)d_in[4];
    const float* b_ih      = (const float*)d_in[5];
    const float* b_hh      = (const float*)d_in[6];
    const float* fc_W      = (const float*)d_in[7];
    const float* fc_b      = (const float*)d_in[8];
    float* out = (float*)d_out;

    cudaFuncSetAttribute(step_kernel, cudaFuncAttributeMaxDynamicSharedMemorySize, SMEM_BYTES);

    prep_weights<<<(N4 * HH) / 256, 256>>>(W_hh, W_ih, b_ih, b_hh, fc_W);
    prep_state<<<(BATCH * HH) / 256, 256>>>(hidden, cell, out, fc_b);

    cudaLaunchAttribute pdl_attr;
    pdl_attr.id = cudaLaunchAttributeProgrammaticStreamSerialization;
    pdl_attr.val.programmaticStreamSerializationAllowed = 1;

    for (int t = 0; t < TT; t++) {
        cudaLaunchConfig_t cfg = {};
        cfg.gridDim = dim3(BATCH / TM, N4 / TN, 1);
        cfg.blockDim = dim3(NTHREADS, 1, 1);
        cfg.dynamicSmemBytes = SMEM_BYTES;
        cfg.stream = 0;
        if (t > 0) { cfg.attrs = &pdl_attr; cfg.numAttrs = 1; }   // t=0 plain: prep must fully finish
        cudaLaunchKernelEx(&cfg, step_kernel, t, future_fd, out);
    }
}

// round 16
// speedup vs baseline: 1.0981x; 1.0011x over previous
#include <cuda_runtime.h>
#include <cuda_fp16.h>
#include <cstdint>

// ============================================================================
// LSTM decoder, B=2048, T=32, H=1024, inference path (pred feedback).
// sm_100: fp16 mma.sync GEMM + cp.async 3-stage pipeline, 2 CTAs/SM.
// R16 = R15 champion + cp.async-staged c-tile:
//  - R13 base: tile 128x128, 8 warps, 2 CTAs/SM, PDL w/ 3-stage B pre-wait
//    prefetch, d_out-folded predsum, smem consts, epilogue unroll 4.
//  - R15: prev/fdv staged to smem during gates-store phase.
//  - R16: g_c tile (16KB) staged via cp.async into spare stage-region smem
//    (overlaps gates STS + prev/fd LDGs); cell loop is now LDS-only on its
//    critical path (co/prev/fdv/consts all smem).
// W columns permuted: col n -> (unit n>>2, gate n&3), gate order i,f,g,o.
// h double-buffered across steps (cross-CTA race fix).
// ============================================================================

#define BATCH 2048
#define TT    32
#define HH    1024
#define N4    4096
#define KE    1024            // K = H (single fp16 term)
#define TM    128             // M tile
#define TN    128             // N tile
#define KC    64              // K chunk (fp16) = 128 bytes
#define NCH   (KE / KC)       // 16
#define NTHREADS 256
#define STAGES 3
#define STAGE_BYTES 32768     // A 16KB + B 16KB
#define STAGING_BYTES 3072    // consts 1664B + prev/fd 1024B
#define SMEM_BYTES  (1024 + STAGES * STAGE_BYTES + STAGING_BYTES)  // ~100KB -> 2 CTAs/SM
#define GPITCH 132            // gates smem pitch (floats), conflict-free
#define CTILE_OFF 73728       // c-tile inside stage region (gates end at 67.6KB)

// Scratch (device globals; no allocation allowed)
__device__ __align__(256) __half g_Wext[(size_t)N4 * KE];        // 8 MB
__device__ __align__(256) __half g_Aext[2][(size_t)BATCH * KE];  // 2 x 4 MB
__device__ __align__(256) float g_c[(size_t)BATCH * HH];         // 8 MB
__device__ __align__(256) float g_bias[N4];
__device__ __align__(256) float g_w0[N4];
__device__ __align__(256) float g_w1[N4];
__device__ __align__(256) float g_fcW[HH];

// ---------------------------------------------------------------------------
// helpers
// ---------------------------------------------------------------------------
__device__ __forceinline__ uint32_t smem_u32(const void* p) {
    uint32_t a;
    asm("{ .reg .u64 t; cvta.to.shared.u64 t, %1; cvt.u32.u64 %0, t; }" : "=r"(a) : "l"(p));
    return a;
}
__device__ __forceinline__ void cp_async16(uint32_t dst, const void* src) {
    asm volatile("cp.async.cg.shared.global [%0], [%1], 16;" :: "r"(dst), "l"(src) : "memory");
}
__device__ __forceinline__ void cp_commit() {
    asm volatile("cp.async.commit_group;" ::: "memory");
}
__device__ __forceinline__ uint32_t sw128(uint32_t off) {
    return off ^ ((off >> 3) & 0x70u);
}
__device__ __forceinline__ void ldsm_x4(uint32_t& r0, uint32_t& r1, uint32_t& r2, uint32_t& r3,
                                        uint32_t addr) {
    asm volatile("ldmatrix.sync.aligned.m8n8.x4.shared.b16 {%0,%1,%2,%3}, [%4];"
                 : "=r"(r0), "=r"(r1), "=r"(r2), "=r"(r3) : "r"(addr));
}
__device__ __forceinline__ void mma_fp16(float* d, const uint32_t* a, const uint32_t* b) {
    asm volatile(
        "mma.sync.aligned.m16n8k16.row.col.f32.f16.f16.f32 "
        "{%0,%1,%2,%3}, {%4,%5,%6,%7}, {%8,%9}, {%0,%1,%2,%3};"
        : "+f"(d[0]), "+f"(d[1]), "+f"(d[2]), "+f"(d[3])
        : "r"(a[0]), "r"(a[1]), "r"(a[2]), "r"(a[3]), "r"(b[0]), "r"(b[1]));
}
__device__ __forceinline__ float sigf(float x) {
    return __fdividef(1.0f, 1.0f + __expf(-x));
}
__device__ __forceinline__ float tanh_f(float x) {
    float xc = fminf(fmaxf(x, -15.0f), 15.0f);
    float e = __expf(2.0f * xc);
    return 1.0f - __fdividef(2.0f, e + 1.0f);
}

// ---------------------------------------------------------------------------
// Prep kernels
// ---------------------------------------------------------------------------
__global__ void prep_weights(const float* __restrict__ W_hh, const float* __restrict__ W_ih,
                             const float* __restrict__ b_ih, const float* __restrict__ b_hh,
                             const float* __restrict__ fc_W) {
    int idx = blockIdx.x * blockDim.x + threadIdx.x;   // 0 .. 4096*1024-1
    int n = idx >> 10, k = idx & 1023;
    int r = (n & 3) * HH + (n >> 2);                   // col n -> orig W_hh row
    g_Wext[(size_t)n * KE + k] = __float2half(W_hh[(size_t)r * HH + k]);
    if (idx < N4) {
        int rr = (idx & 3) * HH + (idx >> 2);
        g_bias[idx] = b_ih[rr] + b_hh[rr];
        g_w0[idx] = W_ih[rr * 2 + 0];
        g_w1[idx] = W_ih[rr * 2 + 1];
    }
    if (idx < HH) g_fcW[idx] = fc_W[idx];
}

__global__ void prep_state(const float* __restrict__ hidden, const float* __restrict__ cell,
                           float* __restrict__ out, const float* __restrict__ fc_b) {
    int idx = blockIdx.x * blockDim.x + threadIdx.x;   // 0 .. 2048*1024-1
    g_c[idx] = cell[idx];
    g_Aext[0][idx] = __float2half(hidden[idx]);
    if (idx < BATCH * TT) out[idx] = fc_b[0];          // predsum accumulates on top
}

// ---------------------------------------------------------------------------
// Step kernel: GEMM (tile 128x128, K=1024) + fused LSTM cell epilogue
// 256 threads = 8 warps; warp tile 64x32: warp_m = wid&1, warp_n = wid>>1.
// ---------------------------------------------------------------------------
__global__ void __launch_bounds__(NTHREADS, 2)
step_kernel(int t, const float* __restrict__ future_fd, float* __restrict__ out) {
    const __half* __restrict__ Asrc = g_Aext[t & 1];
    __half* __restrict__ Adst = g_Aext[(t + 1) & 1];

    extern __shared__ char smem_raw[];
    uint32_t sb = smem_u32(smem_raw);
    uint32_t ab = (sb + 1023u) & ~1023u;
    char* smem = smem_raw + (ab - sb);
    const uint32_t tiles = ab;

    const int tid = threadIdx.x;
    const int wid = tid >> 5;
    const int lid = tid & 31;
    const int wm = wid & 1;          // 0..1  (64-row block)
    const int wn = wid >> 1;         // 0..3  (32-col block)
    const int m0 = blockIdx.x * TM;
    const int n0 = blockIdx.y * TN;
    const int u0 = n0 >> 2;          // first unit of this CTA (32 units)

    // ---- const staging (step-invariant: safe pre-wait) ---------------------
    float4* smB  = (float4*)(smem + STAGES * STAGE_BYTES);   // [32]
    float4* smW0 = smB + 32;
    float4* smW1 = smB + 64;
    float*  smFc = (float*)(smB + 96);                        // [32]
    float*  smPrev = smFc + 32;                               // [128]
    float*  smFd   = smPrev + 128;                            // [128]
    if (tid < 32)        smB[tid]        = ((const float4*)g_bias)[u0 + tid];
    else if (tid < 64)   smW0[tid - 32]  = ((const float4*)g_w0)[u0 + tid - 32];
    else if (tid < 96)   smW1[tid - 64]  = ((const float4*)g_w1)[u0 + tid - 64];
    else if (tid < 128)  smFc[tid - 96]  = g_fcW[u0 + tid - 96];

    // ---- split chunk loaders ----------------------------------------------
    auto load_A = [&](int c, int s) {
        const int k0 = c * KC;
        const uint32_t base = tiles + s * STAGE_BYTES;
        #pragma unroll
        for (int j = 0; j < 4; j++) {
            int li = tid + j * NTHREADS;
            int ri = li >> 3, q = li & 7;
            uint32_t dst = base + sw128((uint32_t)(ri * 128 + q * 16));
            cp_async16(dst, Asrc + ((size_t)(m0 + ri) * KE + k0 + q * 8));
        }
    };
    auto load_B = [&](int c, int s) {
        const int k0 = c * KC;
        const uint32_t base = tiles + s * STAGE_BYTES + 16384;
        #pragma unroll
        for (int j = 0; j < 4; j++) {
            int li = tid + j * NTHREADS;
            int ri = li >> 3, q = li & 7;
            uint32_t dst = base + sw128((uint32_t)(ri * 128 + q * 16));
            cp_async16(dst, g_Wext + ((size_t)(n0 + ri) * KE + k0 + q * 8));
        }
    };

    // ---- PDL prologue: ALL weight stages prefetch pre-wait -----------------
    load_B(0, 0); cp_commit();                 // group: B0
    load_B(1, 1); cp_commit();                 // group: B1
    load_B(2, 2); cp_commit();                 // group: B2
    asm volatile("griddepcontrol.wait;" ::: "memory");
    load_A(0, 0); cp_commit();                 // group: A0
    load_A(1, 1); cp_commit();                 // group: A1

    // ---- lane constants for ldmatrix addressing ----------------------------
    const int a_lr = lid & 15;
    const int a_ch = (lid >> 4) << 4;
    const int b_nr = (lid & 7) + ((lid >> 4) << 3);
    const int b_ch = ((lid >> 3) & 1) << 4;

    float acc[4][4][4];
    #pragma unroll
    for (int i = 0; i < 4; i++)
        #pragma unroll
        for (int j = 0; j < 4; j++)
            #pragma unroll
            for (int r = 0; r < 4; r++) acc[i][j][r] = 0.0f;

    #pragma unroll 1
    for (int c = 0; c < NCH; c++) {
        // c=0: pending {B0,B1,B2,A0,A1}; wait_group 1 retires B0-B2,A0.
        // c=1: retires A1 (A2 may remain). c>=2 steady: retires chunk c's group.
        if (c < NCH - 2) asm volatile("cp.async.wait_group 1;" ::: "memory");
        else             asm volatile("cp.async.wait_group 0;" ::: "memory");
        __syncthreads();

        if (c == 0)              { load_A(2, 2); cp_commit(); }              // B2 already resident
        else if (c + 2 < NCH)    { load_A(c + 2, (c + 2) % STAGES);
                                   load_B(c + 2, (c + 2) % STAGES); cp_commit(); }

        const uint32_t As = tiles + (c % STAGES) * STAGE_BYTES;
        const uint32_t Bs = As + 16384;

        #pragma unroll
        for (int ks = 0; ks < 4; ks++) {
            uint32_t a[4][4], b[4][2];
            #pragma unroll
            for (int mi = 0; mi < 4; mi++) {
                uint32_t off = (uint32_t)((wm * 64 + mi * 16 + a_lr) * 128 + ks * 32 + a_ch);
                ldsm_x4(a[mi][0], a[mi][1], a[mi][2], a[mi][3], As + sw128(off));
            }
            #pragma unroll
            for (int nb = 0; nb < 2; nb++) {
                uint32_t off = (uint32_t)((wn * 32 + nb * 16 + b_nr) * 128 + ks * 32 + b_ch);
                ldsm_x4(b[nb * 2][0], b[nb * 2][1], b[nb * 2 + 1][0], b[nb * 2 + 1][1],
                        Bs + sw128(off));
            }
            #pragma unroll
            for (int mi = 0; mi < 4; mi++)
                #pragma unroll
                for (int j = 0; j < 4; j++)
                    mma_fp16(acc[mi][j], a[mi], b[j]);
        }
    }
    __syncthreads();   // smem stages now reusable as epilogue scratch

    // Next step's CTAs spin up and prefetch weights while we run the epilogue.
    asm volatile("griddepcontrol.launch_dependents;");

    // ---- epilogue staging (all in parallel, latency hidden) ----------------
    //  - c-tile (16KB) via cp.async into spare stage region (past gates)
    //  - prev/fdv scattered LDGs into smem
    //  - gates fragments -> smem
    float* gates = (float*)smem;                     // 128 rows x GPITCH floats
    float* c_s   = (float*)(smem + CTILE_OFF);       // 128 rows x 32 floats
    const int g = lid >> 2, tg = lid & 3;

    {   // c-tile: 128 rows x 128B; 1024 16B-loads over 256 threads
        #pragma unroll
        for (int j = 0; j < 4; j++) {
            int li = tid + j * NTHREADS;
            int ri = li >> 3, q = li & 7;
            cp_async16(tiles + CTILE_OFF + (uint32_t)(ri * 128 + q * 16),
                       g_c + ((size_t)(m0 + ri) * HH + u0 + q * 4));
        }
        cp_commit();
    }
    if (tid < 128) {
        smPrev[tid] = (t > 0) ? out[(m0 + tid) * TT + (t - 1)] : 0.0f;  // includes fc_b
    } else {
        smFd[tid - 128] = future_fd[(m0 + tid - 128) * TT + t];
    }
    {
        const int clb = wn * 32;
        #pragma unroll
        for (int mi = 0; mi < 4; mi++) {
            const int r = wm * 64 + mi * 16 + g;
            #pragma unroll
            for (int j = 0; j < 4; j++) {
                const int cl = clb + j * 8 + 2 * tg;
                *(float2*)&gates[r * GPITCH + cl]       = make_float2(acc[mi][j][0], acc[mi][j][1]);
                *(float2*)&gates[(r + 8) * GPITCH + cl] = make_float2(acc[mi][j][2], acc[mi][j][3]);
            }
        }
    }
    asm volatile("cp.async.wait_group 0;" ::: "memory");
    __syncthreads();

    #pragma unroll 4
    for (int jj = 0; jj < 16; jj++) {
        const int idx = tid + jj * NTHREADS;       // 4096 = 128 rows x 32 units
        const int row = idx >> 5, u = idx & 31;
        const int ug = u0 + u;                     // global unit 0..1023
        const int b = m0 + row;

        float4 gv = *(float4*)&gates[row * GPITCH + 4 * u];
        float4 bs = smB[u];
        float4 w0 = smW0[u];
        float4 w1 = smW1[u];

        const float prev = smPrev[row];
        const float fdv  = smFd[row];

        float gi = gv.x + bs.x + prev * w0.x + fdv * w1.x;
        float gf = gv.y + bs.y + prev * w0.y + fdv * w1.y;
        float gg = gv.z + bs.z + prev * w0.z + fdv * w1.z;
        float go = gv.w + bs.w + prev * w0.w + fdv * w1.w;

        float co = c_s[row * 32 + u];
        float cn = sigf(gf) * co + sigf(gi) * tanh_f(gg);
        float h  = sigf(go) * tanh_f(cn);
        g_c[(size_t)b * HH + ug] = cn;
        Adst[(size_t)b * KE + ug] = __float2half(h);

        float fcp = h * smFc[u];
        #pragma unroll
        for (int o = 16; o; o >>= 1) fcp += __shfl_down_sync(0xFFFFFFFFu, fcp, o);
        if (lid == 0) atomicAdd(&out[b * TT + t], fcp);
    }
}

// ---------------------------------------------------------------------------
// Host launcher
// ---------------------------------------------------------------------------
extern "C" void kernel_launch(void* const* d_in, const int* in_sizes, int n_in,
                              void* d_out, int out_size) {
    const float* future_fd = (const float*)d_in[0];
    const float* hidden    = (const float*)d_in[1];
    const float* cell      = (const float*)d_in[2];
    const float* W_ih      = (const float*)d_in[3];
    const float* W_hh      = (const float*)d_in[4];
    const float* b_ih      = (const float*)d_in[5];
    const float* b_hh      = (const float*)d_in[6];
    const float* fc_W      = (const float*)d_in[7];
    const float* fc_b      = (const float*)d_in[8];
    float* out = (float*)d_out;

    cudaFuncSetAttribute(step_kernel, cudaFuncAttributeMaxDynamicSharedMemorySize, SMEM_BYTES);

    prep_weights<<<(N4 * HH) / 256, 256>>>(W_hh, W_ih, b_ih, b_hh, fc_W);
    prep_state<<<(BATCH * HH) / 256, 256>>>(hidden, cell, out, fc_b);

    cudaLaunchAttribute pdl_attr;
    pdl_attr.id = cudaLaunchAttributeProgrammaticStreamSerialization;
    pdl_attr.val.programmaticStreamSerializationAllowed = 1;

    for (int t = 0; t < TT; t++) {
        cudaLaunchConfig_t cfg = {};
        cfg.gridDim = dim3(BATCH / TM, N4 / TN, 1);
        cfg.blockDim = dim3(NTHREADS, 1, 1);
        cfg.dynamicSmemBytes = SMEM_BYTES;
        cfg.stream = 0;
        if (t > 0) { cfg.attrs = &pdl_attr; cfg.numAttrs = 1; }   // t=0 plain: prep must fully finish
        cudaLaunchKernelEx(&cfg, step_kernel, t, future_fd, out);
    }
}

// round 17
// speedup vs baseline: 1.1519x; 1.0490x over previous
#include <cuda_runtime.h>
#include <cuda_fp16.h>
#include <cstdint>

// ============================================================================
// LSTM decoder, B=2048, T=32, H=1024, inference path (pred feedback).
// sm_100: fp16 mma.sync GEMM + cp.async 3-stage pipeline, 2 CTAs/SM.
// R17 = R16 champion + tanh.approx.f32 activations:
//  - R13 base: tile 128x128, 8 warps, 2 CTAs/SM, PDL w/ 3-stage B pre-wait
//    prefetch, d_out-folded predsum, smem consts, epilogue unroll 4.
//  - R15: prev/fdv staged to smem during gates-store phase.
//  - R16: g_c tile staged via cp.async; cell loop LDS-only critical path.
//  - R17: sigmoid/tanh via single-MUFU tanh.approx.f32 (sig(x)=.5*tanh(x/2)+.5)
//    -> epilogue MUFU work halved; abs err ~1e-4 stays within threshold margin.
// W columns permuted: col n -> (unit n>>2, gate n&3), gate order i,f,g,o.
// h double-buffered across steps (cross-CTA race fix).
// ============================================================================

#define BATCH 2048
#define TT    32
#define HH    1024
#define N4    4096
#define KE    1024            // K = H (single fp16 term)
#define TM    128             // M tile
#define TN    128             // N tile
#define KC    64              // K chunk (fp16) = 128 bytes
#define NCH   (KE / KC)       // 16
#define NTHREADS 256
#define STAGES 3
#define STAGE_BYTES 32768     // A 16KB + B 16KB
#define STAGING_BYTES 3072    // consts 1664B + prev/fd 1024B
#define SMEM_BYTES  (1024 + STAGES * STAGE_BYTES + STAGING_BYTES)  // ~100KB -> 2 CTAs/SM
#define GPITCH 132            // gates smem pitch (floats), conflict-free
#define CTILE_OFF 73728       // c-tile inside stage region (gates end at 67.6KB)

// Scratch (device globals; no allocation allowed)
__device__ __align__(256) __half g_Wext[(size_t)N4 * KE];        // 8 MB
__device__ __align__(256) __half g_Aext[2][(size_t)BATCH * KE];  // 2 x 4 MB
__device__ __align__(256) float g_c[(size_t)BATCH * HH];         // 8 MB
__device__ __align__(256) float g_bias[N4];
__device__ __align__(256) float g_w0[N4];
__device__ __align__(256) float g_w1[N4];
__device__ __align__(256) float g_fcW[HH];

// ---------------------------------------------------------------------------
// helpers
// ---------------------------------------------------------------------------
__device__ __forceinline__ uint32_t smem_u32(const void* p) {
    uint32_t a;
    asm("{ .reg .u64 t; cvta.to.shared.u64 t, %1; cvt.u32.u64 %0, t; }" : "=r"(a) : "l"(p));
    return a;
}
__device__ __forceinline__ void cp_async16(uint32_t dst, const void* src) {
    asm volatile("cp.async.cg.shared.global [%0], [%1], 16;" :: "r"(dst), "l"(src) : "memory");
}
__device__ __forceinline__ void cp_commit() {
    asm volatile("cp.async.commit_group;" ::: "memory");
}
__device__ __forceinline__ uint32_t sw128(uint32_t off) {
    return off ^ ((off >> 3) & 0x70u);
}
__device__ __forceinline__ void ldsm_x4(uint32_t& r0, uint32_t& r1, uint32_t& r2, uint32_t& r3,
                                        uint32_t addr) {
    asm volatile("ldmatrix.sync.aligned.m8n8.x4.shared.b16 {%0,%1,%2,%3}, [%4];"
                 : "=r"(r0), "=r"(r1), "=r"(r2), "=r"(r3) : "r"(addr));
}
__device__ __forceinline__ void mma_fp16(float* d, const uint32_t* a, const uint32_t* b) {
    asm volatile(
        "mma.sync.aligned.m16n8k16.row.col.f32.f16.f16.f32 "
        "{%0,%1,%2,%3}, {%4,%5,%6,%7}, {%8,%9}, {%0,%1,%2,%3};"
        : "+f"(d[0]), "+f"(d[1]), "+f"(d[2]), "+f"(d[3])
        : "r"(a[0]), "r"(a[1]), "r"(a[2]), "r"(a[3]), "r"(b[0]), "r"(b[1]));
}
__device__ __forceinline__ float tanh_fast(float x) {
    float y;
    asm("tanh.approx.f32 %0, %1;" : "=f"(y) : "f"(x));
    return y;
}
__device__ __forceinline__ float sig_fast(float x) {
    return fmaf(tanh_fast(0.5f * x), 0.5f, 0.5f);
}

// ---------------------------------------------------------------------------
// Prep kernels
// ---------------------------------------------------------------------------
__global__ void prep_weights(const float* __restrict__ W_hh, const float* __restrict__ W_ih,
                             const float* __restrict__ b_ih, const float* __restrict__ b_hh,
                             const float* __restrict__ fc_W) {
    int idx = blockIdx.x * blockDim.x + threadIdx.x;   // 0 .. 4096*1024-1
    int n = idx >> 10, k = idx & 1023;
    int r = (n & 3) * HH + (n >> 2);                   // col n -> orig W_hh row
    g_Wext[(size_t)n * KE + k] = __float2half(W_hh[(size_t)r * HH + k]);
    if (idx < N4) {
        int rr = (idx & 3) * HH + (idx >> 2);
        g_bias[idx] = b_ih[rr] + b_hh[rr];
        g_w0[idx] = W_ih[rr * 2 + 0];
        g_w1[idx] = W_ih[rr * 2 + 1];
    }
    if (idx < HH) g_fcW[idx] = fc_W[idx];
}

__global__ void prep_state(const float* __restrict__ hidden, const float* __restrict__ cell,
                           float* __restrict__ out, const float* __restrict__ fc_b) {
    int idx = blockIdx.x * blockDim.x + threadIdx.x;   // 0 .. 2048*1024-1
    g_c[idx] = cell[idx];
    g_Aext[0][idx] = __float2half(hidden[idx]);
    if (idx < BATCH * TT) out[idx] = fc_b[0];          // predsum accumulates on top
}

// ---------------------------------------------------------------------------
// Step kernel: GEMM (tile 128x128, K=1024) + fused LSTM cell epilogue
// 256 threads = 8 warps; warp tile 64x32: warp_m = wid&1, warp_n = wid>>1.
// ---------------------------------------------------------------------------
__global__ void __launch_bounds__(NTHREADS, 2)
step_kernel(int t, const float* __restrict__ future_fd, float* __restrict__ out) {
    const __half* __restrict__ Asrc = g_Aext[t & 1];
    __half* __restrict__ Adst = g_Aext[(t + 1) & 1];

    extern __shared__ char smem_raw[];
    uint32_t sb = smem_u32(smem_raw);
    uint32_t ab = (sb + 1023u) & ~1023u;
    char* smem = smem_raw + (ab - sb);
    const uint32_t tiles = ab;

    const int tid = threadIdx.x;
    const int wid = tid >> 5;
    const int lid = tid & 31;
    const int wm = wid & 1;          // 0..1  (64-row block)
    const int wn = wid >> 1;         // 0..3  (32-col block)
    const int m0 = blockIdx.x * TM;
    const int n0 = blockIdx.y * TN;
    const int u0 = n0 >> 2;          // first unit of this CTA (32 units)

    // ---- const staging (step-invariant: safe pre-wait) ---------------------
    float4* smB  = (float4*)(smem + STAGES * STAGE_BYTES);   // [32]
    float4* smW0 = smB + 32;
    float4* smW1 = smB + 64;
    float*  smFc = (float*)(smB + 96);                        // [32]
    float*  smPrev = smFc + 32;                               // [128]
    float*  smFd   = smPrev + 128;                            // [128]
    if (tid < 32)        smB[tid]        = ((const float4*)g_bias)[u0 + tid];
    else if (tid < 64)   smW0[tid - 32]  = ((const float4*)g_w0)[u0 + tid - 32];
    else if (tid < 96)   smW1[tid - 64]  = ((const float4*)g_w1)[u0 + tid - 64];
    else if (tid < 128)  smFc[tid - 96]  = g_fcW[u0 + tid - 96];

    // ---- split chunk loaders ----------------------------------------------
    auto load_A = [&](int c, int s) {
        const int k0 = c * KC;
        const uint32_t base = tiles + s * STAGE_BYTES;
        #pragma unroll
        for (int j = 0; j < 4; j++) {
            int li = tid + j * NTHREADS;
            int ri = li >> 3, q = li & 7;
            uint32_t dst = base + sw128((uint32_t)(ri * 128 + q * 16));
            cp_async16(dst, Asrc + ((size_t)(m0 + ri) * KE + k0 + q * 8));
        }
    };
    auto load_B = [&](int c, int s) {
        const int k0 = c * KC;
        const uint32_t base = tiles + s * STAGE_BYTES + 16384;
        #pragma unroll
        for (int j = 0; j < 4; j++) {
            int li = tid + j * NTHREADS;
            int ri = li >> 3, q = li & 7;
            uint32_t dst = base + sw128((uint32_t)(ri * 128 + q * 16));
            cp_async16(dst, g_Wext + ((size_t)(n0 + ri) * KE + k0 + q * 8));
        }
    };

    // ---- PDL prologue: ALL weight stages prefetch pre-wait -----------------
    load_B(0, 0); cp_commit();                 // group: B0
    load_B(1, 1); cp_commit();                 // group: B1
    load_B(2, 2); cp_commit();                 // group: B2
    asm volatile("griddepcontrol.wait;" ::: "memory");
    load_A(0, 0); cp_commit();                 // group: A0
    load_A(1, 1); cp_commit();                 // group: A1

    // ---- lane constants for ldmatrix addressing ----------------------------
    const int a_lr = lid & 15;
    const int a_ch = (lid >> 4) << 4;
    const int b_nr = (lid & 7) + ((lid >> 4) << 3);
    const int b_ch = ((lid >> 3) & 1) << 4;

    float acc[4][4][4];
    #pragma unroll
    for (int i = 0; i < 4; i++)
        #pragma unroll
        for (int j = 0; j < 4; j++)
            #pragma unroll
            for (int r = 0; r < 4; r++) acc[i][j][r] = 0.0f;

    #pragma unroll 1
    for (int c = 0; c < NCH; c++) {
        // c=0: pending {B0,B1,B2,A0,A1}; wait_group 1 retires B0-B2,A0.
        // c=1: retires A1 (A2 may remain). c>=2 steady: retires chunk c's group.
        if (c < NCH - 2) asm volatile("cp.async.wait_group 1;" ::: "memory");
        else             asm volatile("cp.async.wait_group 0;" ::: "memory");
        __syncthreads();

        if (c == 0)              { load_A(2, 2); cp_commit(); }              // B2 already resident
        else if (c + 2 < NCH)    { load_A(c + 2, (c + 2) % STAGES);
                                   load_B(c + 2, (c + 2) % STAGES); cp_commit(); }

        const uint32_t As = tiles + (c % STAGES) * STAGE_BYTES;
        const uint32_t Bs = As + 16384;

        #pragma unroll
        for (int ks = 0; ks < 4; ks++) {
            uint32_t a[4][4], b[4][2];
            #pragma unroll
            for (int mi = 0; mi < 4; mi++) {
                uint32_t off = (uint32_t)((wm * 64 + mi * 16 + a_lr) * 128 + ks * 32 + a_ch);
                ldsm_x4(a[mi][0], a[mi][1], a[mi][2], a[mi][3], As + sw128(off));
            }
            #pragma unroll
            for (int nb = 0; nb < 2; nb++) {
                uint32_t off = (uint32_t)((wn * 32 + nb * 16 + b_nr) * 128 + ks * 32 + b_ch);
                ldsm_x4(b[nb * 2][0], b[nb * 2][1], b[nb * 2 + 1][0], b[nb * 2 + 1][1],
                        Bs + sw128(off));
            }
            #pragma unroll
            for (int mi = 0; mi < 4; mi++)
                #pragma unroll
                for (int j = 0; j < 4; j++)
                    mma_fp16(acc[mi][j], a[mi], b[j]);
        }
    }
    __syncthreads();   // smem stages now reusable as epilogue scratch

    // Next step's CTAs spin up and prefetch weights while we run the epilogue.
    asm volatile("griddepcontrol.launch_dependents;");

    // ---- epilogue staging (all in parallel, latency hidden) ----------------
    float* gates = (float*)smem;                     // 128 rows x GPITCH floats
    float* c_s   = (float*)(smem + CTILE_OFF);       // 128 rows x 32 floats
    const int g = lid >> 2, tg = lid & 3;

    {   // c-tile: 128 rows x 128B; 1024 16B-loads over 256 threads
        #pragma unroll
        for (int j = 0; j < 4; j++) {
            int li = tid + j * NTHREADS;
            int ri = li >> 3, q = li & 7;
            cp_async16(tiles + CTILE_OFF + (uint32_t)(ri * 128 + q * 16),
                       g_c + ((size_t)(m0 + ri) * HH + u0 + q * 4));
        }
        cp_commit();
    }
    if (tid < 128) {
        smPrev[tid] = (t > 0) ? out[(m0 + tid) * TT + (t - 1)] : 0.0f;  // includes fc_b
    } else {
        smFd[tid - 128] = future_fd[(m0 + tid - 128) * TT + t];
    }
    {
        const int clb = wn * 32;
        #pragma unroll
        for (int mi = 0; mi < 4; mi++) {
            const int r = wm * 64 + mi * 16 + g;
            #pragma unroll
            for (int j = 0; j < 4; j++) {
                const int cl = clb + j * 8 + 2 * tg;
                *(float2*)&gates[r * GPITCH + cl]       = make_float2(acc[mi][j][0], acc[mi][j][1]);
                *(float2*)&gates[(r + 8) * GPITCH + cl] = make_float2(acc[mi][j][2], acc[mi][j][3]);
            }
        }
    }
    asm volatile("cp.async.wait_group 0;" ::: "memory");
    __syncthreads();

    #pragma unroll 4
    for (int jj = 0; jj < 16; jj++) {
        const int idx = tid + jj * NTHREADS;       // 4096 = 128 rows x 32 units
        const int row = idx >> 5, u = idx & 31;
        const int ug = u0 + u;                     // global unit 0..1023
        const int b = m0 + row;

        float4 gv = *(float4*)&gates[row * GPITCH + 4 * u];
        float4 bs = smB[u];
        float4 w0 = smW0[u];
        float4 w1 = smW1[u];

        const float prev = smPrev[row];
        const float fdv  = smFd[row];

        float gi = gv.x + bs.x + prev * w0.x + fdv * w1.x;
        float gf = gv.y + bs.y + prev * w0.y + fdv * w1.y;
        float gg = gv.z + bs.z + prev * w0.z + fdv * w1.z;
        float go = gv.w + bs.w + prev * w0.w + fdv * w1.w;

        float co = c_s[row * 32 + u];
        float cn = sig_fast(gf) * co + sig_fast(gi) * tanh_fast(gg);
        float h  = sig_fast(go) * tanh_fast(cn);
        g_c[(size_t)b * HH + ug] = cn;
        Adst[(size_t)b * KE + ug] = __float2half(h);

        float fcp = h * smFc[u];
        #pragma unroll
        for (int o = 16; o; o >>= 1) fcp += __shfl_down_sync(0xFFFFFFFFu, fcp, o);
        if (lid == 0) atomicAdd(&out[b * TT + t], fcp);
    }
}

// ---------------------------------------------------------------------------
// Host launcher
// ---------------------------------------------------------------------------
extern "C" void kernel_launch(void* const* d_in, const int* in_sizes, int n_in,
                              void* d_out, int out_size) {
    const float* future_fd = (const float*)d_in[0];
    const float* hidden    = (const float*)d_in[1];
    const float* cell      = (const float*)d_in[2];
    const float* W_ih      = (const float*)d_in[3];
    const float* W_hh      = (const float*)d_in[4];
    const float* b_ih      = (const float*)d_in[5];
    const float* b_hh      = (const float*)d_in[6];
    const float* fc_W      = (const float*)d_in[7];
    const float* fc_b      = (const float*)d_in[8];
    float* out = (float*)d_out;

    cudaFuncSetAttribute(step_kernel, cudaFuncAttributeMaxDynamicSharedMemorySize, SMEM_BYTES);

    prep_weights<<<(N4 * HH) / 256, 256>>>(W_hh, W_ih, b_ih, b_hh, fc_W);
    prep_state<<<(BATCH * HH) / 256, 256>>>(hidden, cell, out, fc_b);

    cudaLaunchAttribute pdl_attr;
    pdl_attr.id = cudaLaunchAttributeProgrammaticStreamSerialization;
    pdl_attr.val.programmaticStreamSerializationAllowed = 1;

    for (int t = 0; t < TT; t++) {
        cudaLaunchConfig_t cfg = {};
        cfg.gridDim = dim3(BATCH / TM, N4 / TN, 1);
        cfg.blockDim = dim3(NTHREADS, 1, 1);
        cfg.dynamicSmemBytes = SMEM_BYTES;
        cfg.stream = 0;
        if (t > 0) { cfg.attrs = &pdl_attr; cfg.numAttrs = 1; }   // t=0 plain: prep must fully finish
        cudaLaunchKernelEx(&cfg, step_kernel, t, future_fd, out);
    }
}